// round 1
// baseline (speedup 1.0000x reference)
#include <cuda_runtime.h>
#include <math.h>

#define NNODE 50000
#define NEDGE 800000
#define ND    128
#define NH    8
#define DKK   16
#define FFD   512

// ---------------- scratch (static device allocations, no runtime alloc) ----------------
__device__ float g_q [NNODE * ND];
__device__ float g_k [NNODE * ND];
__device__ float g_v [NNODE * ND];
__device__ float g_wv[NNODE * ND];
__device__ float g_z [NNODE * NH];
__device__ float g_t0[NNODE * ND];   // pre-LN accumulator
__device__ float g_t1[NNODE * ND];   // post-LN1 "out"
__device__ float g_ff[NNODE * FFD];
__device__ float g_x1[NNODE * ND];   // layer-0 output

// ---------------- fused linear: C = A @ W^T (+bias)(+res)(relu) ----------------
// A: M x K row-major, W: NOUT x K row-major. Block tile 64(M) x 128(N), 256 thr,
// thread tile 8x4. fp32 accumulate.
template<int K, bool RELU, bool BIAS, bool RES>
__global__ __launch_bounds__(256) void linear_kernel(
    const float* __restrict__ A, const float* __restrict__ W,
    const float* __restrict__ bias, const float* __restrict__ res,
    float* __restrict__ C, int M, int NOUT)
{
    __shared__ float As[16][65];
    __shared__ float Bs[16][132];
    const int bm = blockIdx.x * 64;
    const int bn = blockIdx.y * 128;
    const int tid = threadIdx.x;
    const int tx = tid & 31;   // covers cols tx*4 .. tx*4+3
    const int ty = tid >> 5;   // covers rows ty*8 .. ty*8+7

    float acc[8][4];
#pragma unroll
    for (int i = 0; i < 8; i++)
#pragma unroll
        for (int j = 0; j < 4; j++) acc[i][j] = 0.f;

    for (int k0 = 0; k0 < K; k0 += 16) {
        // A tile: 64x16
#pragma unroll
        for (int i = 0; i < 4; i++) {
            int idx = tid + i * 256;
            int m = idx >> 4, kk = idx & 15;
            int gm = bm + m;
            As[kk][m] = (gm < M) ? A[(long)gm * K + k0 + kk] : 0.f;
        }
        // W tile: 128 rows x 16 k  -> Bs[k][n]
#pragma unroll
        for (int i = 0; i < 8; i++) {
            int idx = tid + i * 256;
            int n = idx >> 4, kk = idx & 15;
            Bs[kk][n] = W[(long)(bn + n) * K + k0 + kk];
        }
        __syncthreads();
#pragma unroll
        for (int kk = 0; kk < 16; kk++) {
            float4 b4 = *(const float4*)&Bs[kk][tx * 4];
#pragma unroll
            for (int i = 0; i < 8; i++) {
                float a = As[kk][ty * 8 + i];
                acc[i][0] += a * b4.x;
                acc[i][1] += a * b4.y;
                acc[i][2] += a * b4.z;
                acc[i][3] += a * b4.w;
            }
        }
        __syncthreads();
    }

    float4 bia = make_float4(0.f, 0.f, 0.f, 0.f);
    if (BIAS) bia = *(const float4*)&bias[bn + tx * 4];
#pragma unroll
    for (int i = 0; i < 8; i++) {
        int gm = bm + ty * 8 + i;
        if (gm < M) {
            float4 c;
            c.x = acc[i][0]; c.y = acc[i][1]; c.z = acc[i][2]; c.w = acc[i][3];
            if (BIAS) { c.x += bia.x; c.y += bia.y; c.z += bia.z; c.w += bia.w; }
            if (RES) {
                float4 r = *(const float4*)&res[(long)gm * NOUT + bn + tx * 4];
                c.x += r.x; c.y += r.y; c.z += r.z; c.w += r.w;
            }
            if (RELU) {
                c.x = fmaxf(c.x, 0.f); c.y = fmaxf(c.y, 0.f);
                c.z = fmaxf(c.z, 0.f); c.w = fmaxf(c.w, 0.f);
            }
            *(float4*)&C[(long)gm * NOUT + bn + tx * 4] = c;
        }
    }
}

// ---------------- zero wv / z ----------------
__global__ void zero_kernel()
{
    int i = blockIdx.x * blockDim.x + threadIdx.x;
    if (i < NNODE * ND) g_wv[i] = 0.f;
    if (i < NNODE * NH) g_z[i] = 0.f;
}

// ---------------- edge attention + segment sum (one warp per edge) ----------------
__global__ __launch_bounds__(256) void edge_kernel(
    const int* __restrict__ edges, const int* __restrict__ src,
    const int* __restrict__ dst, const float* __restrict__ rel, int E)
{
    int warp = (blockIdx.x * blockDim.x + threadIdx.x) >> 5;
    int lane = threadIdx.x & 31;
    if (warp >= E) return;

    int s = src[warp];
    int d = dst[warp];
    int r = edges[warp];

    // lane covers feature indices j = 4*lane .. 4*lane+3;  h = lane>>2, dk = 4*(lane&3)
    const float4 e4 = *(const float4*)&rel[(long)r * DKK + (lane & 3) * 4];
    const float4 k4 = *(const float4*)&g_k[(long)s * ND + lane * 4];
    const float4 q4 = *(const float4*)&g_q[(long)d * ND + lane * 4];

    float p = (k4.x + e4.x) * q4.x + (k4.y + e4.y) * q4.y +
              (k4.z + e4.z) * q4.z + (k4.w + e4.w) * q4.w;
    p += __shfl_xor_sync(0xffffffffu, p, 1);
    p += __shfl_xor_sync(0xffffffffu, p, 2);   // per-head score in all 4 lanes of group

    float sc = expf(fminf(fmaxf(p * 0.25f, -5.f), 5.f));

    const float4 v4 = *(const float4*)&g_v[(long)s * ND + lane * 4];
    float4 m;
    m.x = (v4.x + e4.x) * sc;
    m.y = (v4.y + e4.y) * sc;
    m.z = (v4.z + e4.z) * sc;
    m.w = (v4.w + e4.w) * sc;

    float* wp = &g_wv[(long)d * ND + lane * 4];
    asm volatile("red.global.add.v4.f32 [%0], {%1,%2,%3,%4};"
                 :: "l"(__cvta_generic_to_global(wp)),
                    "f"(m.x), "f"(m.y), "f"(m.z), "f"(m.w)
                 : "memory");
    if ((lane & 3) == 0)
        atomicAdd(&g_z[(long)d * NH + (lane >> 2)], sc);
}

// ---------------- o = wv / z (in place) ----------------
__global__ void finalize_kernel()
{
    int i = blockIdx.x * blockDim.x + threadIdx.x;
    if (i >= NNODE * ND) return;
    int row = i >> 7;
    int h   = (i >> 4) & 7;
    g_wv[i] = g_wv[i] / g_z[row * NH + h];
}

// ---------------- LayerNorm over last dim (128), one warp per row ----------------
__global__ __launch_bounds__(256) void ln_kernel(
    const float* __restrict__ X, const float* __restrict__ gam,
    const float* __restrict__ bet, float* __restrict__ Y, int M)
{
    int row  = (blockIdx.x * blockDim.x + threadIdx.x) >> 5;
    int lane = threadIdx.x & 31;
    if (row >= M) return;

    float4 x = *(const float4*)&X[(long)row * ND + lane * 4];
    float s = x.x + x.y + x.z + x.w;
#pragma unroll
    for (int o = 16; o; o >>= 1) s += __shfl_xor_sync(0xffffffffu, s, o);
    float m = s * (1.f / 128.f);
    float dx = x.x - m, dy = x.y - m, dz = x.z - m, dw = x.w - m;
    float vv = dx * dx + dy * dy + dz * dz + dw * dw;
#pragma unroll
    for (int o = 16; o; o >>= 1) vv += __shfl_xor_sync(0xffffffffu, vv, o);
    float inv = rsqrtf(vv * (1.f / 128.f) + 1e-5f);

    float4 g = *(const float4*)&gam[lane * 4];
    float4 b = *(const float4*)&bet[lane * 4];
    float4 y;
    y.x = dx * inv * g.x + b.x;
    y.y = dy * inv * g.y + b.y;
    y.z = dz * inv * g.z + b.z;
    y.w = dw * inv * g.w + b.w;
    *(float4*)&Y[(long)row * ND + lane * 4] = y;
}

// ---------------- host driver ----------------
extern "C" void kernel_launch(void* const* d_in, const int* in_sizes, int n_in,
                              void* d_out, int out_size)
{
    const float* x     = (const float*)d_in[0];
    const int*   edges = (const int*)  d_in[1];
    const int*   src   = (const int*)  d_in[2];
    const int*   dst   = (const int*)  d_in[3];
    const float* rel   = (const float*)d_in[4];
    const float* Wq    = (const float*)d_in[5];
    const float* bq    = (const float*)d_in[6];
    const float* Wk    = (const float*)d_in[7];
    const float* Wv    = (const float*)d_in[8];
    const float* Wo    = (const float*)d_in[9];
    const float* bo    = (const float*)d_in[10];
    const float* ln1g  = (const float*)d_in[11];
    const float* ln1b  = (const float*)d_in[12];
    const float* W1    = (const float*)d_in[13];
    const float* b1    = (const float*)d_in[14];
    const float* W2    = (const float*)d_in[15];
    const float* b2    = (const float*)d_in[16];
    const float* ln2g  = (const float*)d_in[17];
    const float* ln2b  = (const float*)d_in[18];

    const int M = NNODE;
    const int E = NEDGE;

    float *q, *k, *v, *wv, *t0, *t1, *ff, *x1;
    cudaGetSymbolAddress((void**)&q,  g_q);
    cudaGetSymbolAddress((void**)&k,  g_k);
    cudaGetSymbolAddress((void**)&v,  g_v);
    cudaGetSymbolAddress((void**)&wv, g_wv);
    cudaGetSymbolAddress((void**)&t0, g_t0);
    cudaGetSymbolAddress((void**)&t1, g_t1);
    cudaGetSymbolAddress((void**)&ff, g_ff);
    cudaGetSymbolAddress((void**)&x1, g_x1);

    dim3 g64((M + 63) / 64, 1);
    dim3 g64x4((M + 63) / 64, 4);
    int zeroBlocks = (M * ND + 255) / 256;
    int edgeBlocks = (E + 7) / 8;            // one warp per edge, 8 warps/block
    int lnBlocks   = (M + 7) / 8;            // one warp per row

    const float* xin = x;
    for (int li = 0; li < 2; li++) {
        float* xout = (li == 0) ? x1 : (float*)d_out;
        const float* wWq = Wq + (long)li * ND * ND;
        const float* wWk = Wk + (long)li * ND * ND;
        const float* wWv = Wv + (long)li * ND * ND;
        const float* wWo = Wo + (long)li * ND * ND;
        const float* wW1 = W1 + (long)li * FFD * ND;
        const float* wW2 = W2 + (long)li * ND * FFD;

        // projections
        linear_kernel<ND, false, true,  false><<<g64, 256>>>(xin, wWq, bq + li * ND, nullptr, q, M, ND);
        linear_kernel<ND, false, false, false><<<g64, 256>>>(xin, wWk, nullptr,      nullptr, k, M, ND);
        linear_kernel<ND, false, false, false><<<g64, 256>>>(xin, wWv, nullptr,      nullptr, v, M, ND);

        // attention aggregation
        zero_kernel<<<zeroBlocks, 256>>>();
        edge_kernel<<<edgeBlocks, 256>>>(edges, src, dst, rel, E);
        finalize_kernel<<<zeroBlocks, 256>>>();

        // output proj + residual, LN1
        linear_kernel<ND, false, true, true><<<g64, 256>>>(wv, wWo, bo + li * ND, xin, t0, M, ND);
        ln_kernel<<<lnBlocks, 256>>>(t0, ln1g + li * ND, ln1b + li * ND, t1, M);

        // FFN
        linear_kernel<ND,  true,  true, false><<<g64x4, 256>>>(t1, wW1, b1 + li * FFD, nullptr, ff, M, FFD);
        linear_kernel<FFD, false, true, true ><<<g64,   256>>>(ff, wW2, b2 + li * ND,  t1,     t0, M, ND);
        ln_kernel<<<lnBlocks, 256>>>(t0, ln2g + li * ND, ln2b + li * ND, xout, M);

        xin = xout;
    }
}

// round 2
// speedup vs baseline: 1.9799x; 1.9799x over previous
#include <cuda_runtime.h>
#include <math.h>
#include <stdint.h>

#define NNODE 50000
#define NEDGE 800000
#define ND    128
#define NH    8
#define DKK   16
#define FFD   512

// ---------------- scratch ----------------
__device__ float g_q [NNODE * ND];
__device__ float g_k [NNODE * ND];
__device__ float g_v [NNODE * ND];
__device__ float g_wv[NNODE * ND];
__device__ float g_z [NNODE * NH];
__device__ float g_t0[NNODE * ND];
__device__ float g_t1[NNODE * ND];
__device__ float g_ff[NNODE * FFD];
__device__ float g_x1[NNODE * ND];

// ---------------- tf32 helpers ----------------
__device__ __forceinline__ uint32_t f2tf32(float x) {
    uint32_t r;
    asm("cvt.rna.tf32.f32 %0, %1;" : "=r"(r) : "f"(x));
    return r;
}

__device__ __forceinline__ void mma_tf32(float* c, const uint32_t* a, const uint32_t* b) {
    asm volatile(
        "mma.sync.aligned.m16n8k8.row.col.f32.tf32.tf32.f32 "
        "{%0,%1,%2,%3}, {%4,%5,%6,%7}, {%8,%9}, {%0,%1,%2,%3};"
        : "+f"(c[0]), "+f"(c[1]), "+f"(c[2]), "+f"(c[3])
        : "r"(a[0]), "r"(a[1]), "r"(a[2]), "r"(a[3]),
          "r"(b[0]), "r"(b[1]));
}

// ---------------- TF32 GEMM: C = X @ W^T (+bias)(+res)(relu) ----------------
// Computes C^T = W @ X^T internally: both operands K-contiguous row-major.
// Block tile: 128 m x 128 n, KC=64 chunks, 8 warps (4 n-warps x 2 m-warps),
// warp tile 32n x 64m => 2x8 m16n8k8 mma tiles.
#define KC 64
#define SK 68            // smem row stride (floats): (4*row + k) % 32 conflict-free
#define SN 132           // epilogue smem stride
#define GEMM_SMEM_BYTES (2 * 128 * SK * 4)   // 69632 B (>= 128*SN*4 = 67584)

template<bool RELU, bool BIAS, bool RES>
__global__ __launch_bounds__(256) void gemm_tf32_kernel(
    const float* __restrict__ X, const float* __restrict__ W,
    const float* __restrict__ bias, const float* __restrict__ res,
    float* __restrict__ C, int M, int K, int NOUT)
{
    extern __shared__ uint32_t smem[];
    uint32_t* Ws = smem;                 // [128 n][SK]
    uint32_t* Xs = smem + 128 * SK;      // [128 m][SK]

    const int bm = blockIdx.x * 128;
    const int bn = blockIdx.y * 128;
    const int tid  = threadIdx.x;
    const int lane = tid & 31;
    const int wid  = tid >> 5;
    const int g    = lane >> 2;          // 0..7
    const int tig  = lane & 3;           // 0..3
    const int wn   = (wid & 3) * 32;     // warp n base
    const int wm   = (wid >> 2) * 64;    // warp m base

    float c[2][8][4];
#pragma unroll
    for (int i = 0; i < 2; i++)
#pragma unroll
        for (int j = 0; j < 8; j++)
#pragma unroll
            for (int t = 0; t < 4; t++) c[i][j][t] = 0.f;

    for (int k0 = 0; k0 < K; k0 += KC) {
        // stage W tile: 128 rows (n) x 64 k
#pragma unroll
        for (int i = 0; i < 8; i++) {
            int idx = tid + i * 256;             // 0..2047
            int r = idx >> 4, cq = idx & 15;
            float4 w4 = *(const float4*)&W[(bn + r) * K + k0 + cq * 4];
            uint32_t* p = &Ws[r * SK + cq * 4];
            p[0] = f2tf32(w4.x); p[1] = f2tf32(w4.y);
            p[2] = f2tf32(w4.z); p[3] = f2tf32(w4.w);
        }
        // stage X tile: 128 rows (m) x 64 k, guarded
#pragma unroll
        for (int i = 0; i < 8; i++) {
            int idx = tid + i * 256;
            int r = idx >> 4, cq = idx & 15;
            int gm = bm + r;
            float4 x4 = make_float4(0.f, 0.f, 0.f, 0.f);
            if (gm < M) x4 = *(const float4*)&X[gm * K + k0 + cq * 4];
            uint32_t* p = &Xs[r * SK + cq * 4];
            p[0] = f2tf32(x4.x); p[1] = f2tf32(x4.y);
            p[2] = f2tf32(x4.z); p[3] = f2tf32(x4.w);
        }
        __syncthreads();

#pragma unroll
        for (int ks = 0; ks < KC / 8; ks++) {
            const int kk = ks * 8;
            uint32_t a[2][4];
#pragma unroll
            for (int tn = 0; tn < 2; tn++) {
                int row = wn + tn * 16 + g;
                a[tn][0] = Ws[row * SK + kk + tig];
                a[tn][1] = Ws[(row + 8) * SK + kk + tig];
                a[tn][2] = Ws[row * SK + kk + tig + 4];
                a[tn][3] = Ws[(row + 8) * SK + kk + tig + 4];
            }
            uint32_t b[8][2];
#pragma unroll
            for (int tm = 0; tm < 8; tm++) {
                int col = wm + tm * 8 + g;
                b[tm][0] = Xs[col * SK + kk + tig];
                b[tm][1] = Xs[col * SK + kk + tig + 4];
            }
#pragma unroll
            for (int tn = 0; tn < 2; tn++)
#pragma unroll
                for (int tm = 0; tm < 8; tm++)
                    mma_tf32(c[tn][tm], a[tn], b[tm]);
        }
        __syncthreads();
    }

    // epilogue: transpose through smem, then coalesced writes
    float* Cs = (float*)smem;            // [128 m][SN]
#pragma unroll
    for (int tn = 0; tn < 2; tn++)
#pragma unroll
        for (int tm = 0; tm < 8; tm++) {
            int n = wn + tn * 16 + g;
            int m = wm + tm * 8 + tig * 2;
            Cs[m * SN + n]           = c[tn][tm][0];
            Cs[(m + 1) * SN + n]     = c[tn][tm][1];
            Cs[m * SN + n + 8]       = c[tn][tm][2];
            Cs[(m + 1) * SN + n + 8] = c[tn][tm][3];
        }
    __syncthreads();

#pragma unroll
    for (int i = 0; i < 16; i++) {
        int idx = tid + i * 256;             // 0..4095
        int mm = idx >> 5, nq = idx & 31;
        int gm = bm + mm;
        if (gm >= M) continue;
        float4 cv = *(float4*)&Cs[mm * SN + nq * 4];
        if (BIAS) {
            float4 b4 = *(const float4*)&bias[bn + nq * 4];
            cv.x += b4.x; cv.y += b4.y; cv.z += b4.z; cv.w += b4.w;
        }
        if (RES) {
            float4 r4 = *(const float4*)&res[gm * NOUT + bn + nq * 4];
            cv.x += r4.x; cv.y += r4.y; cv.z += r4.z; cv.w += r4.w;
        }
        if (RELU) {
            cv.x = fmaxf(cv.x, 0.f); cv.y = fmaxf(cv.y, 0.f);
            cv.z = fmaxf(cv.z, 0.f); cv.w = fmaxf(cv.w, 0.f);
        }
        *(float4*)&C[gm * NOUT + bn + nq * 4] = cv;
    }
}

// ---------------- edge attention + segment sum (one warp per edge) ----------------
__global__ __launch_bounds__(256) void edge_kernel(
    const int* __restrict__ edges, const int* __restrict__ src,
    const int* __restrict__ dst, const float* __restrict__ rel, int E)
{
    int warp = (blockIdx.x * blockDim.x + threadIdx.x) >> 5;
    int lane = threadIdx.x & 31;
    if (warp >= E) return;

    int s = src[warp];
    int d = dst[warp];
    int r = edges[warp];

    const float4 e4 = *(const float4*)&rel[(long)r * DKK + (lane & 3) * 4];
    const float4 k4 = *(const float4*)&g_k[(long)s * ND + lane * 4];
    const float4 q4 = *(const float4*)&g_q[(long)d * ND + lane * 4];

    float p = (k4.x + e4.x) * q4.x + (k4.y + e4.y) * q4.y +
              (k4.z + e4.z) * q4.z + (k4.w + e4.w) * q4.w;
    p += __shfl_xor_sync(0xffffffffu, p, 1);
    p += __shfl_xor_sync(0xffffffffu, p, 2);

    float sc = expf(fminf(fmaxf(p * 0.25f, -5.f), 5.f));

    const float4 v4 = *(const float4*)&g_v[(long)s * ND + lane * 4];
    float4 m;
    m.x = (v4.x + e4.x) * sc;
    m.y = (v4.y + e4.y) * sc;
    m.z = (v4.z + e4.z) * sc;
    m.w = (v4.w + e4.w) * sc;

    float* wp = &g_wv[(long)d * ND + lane * 4];
    asm volatile("red.global.add.v4.f32 [%0], {%1,%2,%3,%4};"
                 :: "l"(__cvta_generic_to_global(wp)),
                    "f"(m.x), "f"(m.y), "f"(m.z), "f"(m.w)
                 : "memory");
    if ((lane & 3) == 0)
        atomicAdd(&g_z[(long)d * NH + (lane >> 2)], sc);
}

// ---------------- o = wv / z (in place) ----------------
__global__ void finalize_kernel()
{
    int i = blockIdx.x * blockDim.x + threadIdx.x;
    if (i >= NNODE * ND) return;
    int row = i >> 7;
    int h   = (i >> 4) & 7;
    g_wv[i] = g_wv[i] / g_z[row * NH + h];
}

// ---------------- LayerNorm over last dim (128) ----------------
__global__ __launch_bounds__(256) void ln_kernel(
    const float* __restrict__ X, const float* __restrict__ gam,
    const float* __restrict__ bet, float* __restrict__ Y, int M)
{
    int row  = (blockIdx.x * blockDim.x + threadIdx.x) >> 5;
    int lane = threadIdx.x & 31;
    if (row >= M) return;

    float4 x = *(const float4*)&X[(long)row * ND + lane * 4];
    float s = x.x + x.y + x.z + x.w;
#pragma unroll
    for (int o = 16; o; o >>= 1) s += __shfl_xor_sync(0xffffffffu, s, o);
    float m = s * (1.f / 128.f);
    float dx = x.x - m, dy = x.y - m, dz = x.z - m, dw = x.w - m;
    float vv = dx * dx + dy * dy + dz * dz + dw * dw;
#pragma unroll
    for (int o = 16; o; o >>= 1) vv += __shfl_xor_sync(0xffffffffu, vv, o);
    float inv = rsqrtf(vv * (1.f / 128.f) + 1e-5f);

    float4 g4 = *(const float4*)&gam[lane * 4];
    float4 b4 = *(const float4*)&bet[lane * 4];
    float4 y;
    y.x = dx * inv * g4.x + b4.x;
    y.y = dy * inv * g4.y + b4.y;
    y.z = dz * inv * g4.z + b4.z;
    y.w = dw * inv * g4.w + b4.w;
    *(float4*)&Y[(long)row * ND + lane * 4] = y;
}

// ---------------- host driver ----------------
extern "C" void kernel_launch(void* const* d_in, const int* in_sizes, int n_in,
                              void* d_out, int out_size)
{
    const float* x     = (const float*)d_in[0];
    const int*   edges = (const int*)  d_in[1];
    const int*   src   = (const int*)  d_in[2];
    const int*   dst   = (const int*)  d_in[3];
    const float* rel   = (const float*)d_in[4];
    const float* Wq    = (const float*)d_in[5];
    const float* bq    = (const float*)d_in[6];
    const float* Wk    = (const float*)d_in[7];
    const float* Wv    = (const float*)d_in[8];
    const float* Wo    = (const float*)d_in[9];
    const float* bo    = (const float*)d_in[10];
    const float* ln1g  = (const float*)d_in[11];
    const float* ln1b  = (const float*)d_in[12];
    const float* W1    = (const float*)d_in[13];
    const float* b1    = (const float*)d_in[14];
    const float* W2    = (const float*)d_in[15];
    const float* b2    = (const float*)d_in[16];
    const float* ln2g  = (const float*)d_in[17];
    const float* ln2b  = (const float*)d_in[18];

    const int M = NNODE;
    const int E = NEDGE;

    float *q, *k, *v, *wv, *z, *t0, *t1, *ff, *x1;
    cudaGetSymbolAddress((void**)&q,  g_q);
    cudaGetSymbolAddress((void**)&k,  g_k);
    cudaGetSymbolAddress((void**)&v,  g_v);
    cudaGetSymbolAddress((void**)&wv, g_wv);
    cudaGetSymbolAddress((void**)&z,  g_z);
    cudaGetSymbolAddress((void**)&t0, g_t0);
    cudaGetSymbolAddress((void**)&t1, g_t1);
    cudaGetSymbolAddress((void**)&ff, g_ff);
    cudaGetSymbolAddress((void**)&x1, g_x1);

    // opt-in to >48KB dynamic smem (host-side, idempotent, not a graph op)
    cudaFuncSetAttribute(gemm_tf32_kernel<false, true,  false>,
        cudaFuncAttributeMaxDynamicSharedMemorySize, GEMM_SMEM_BYTES);
    cudaFuncSetAttribute(gemm_tf32_kernel<false, false, false>,
        cudaFuncAttributeMaxDynamicSharedMemorySize, GEMM_SMEM_BYTES);
    cudaFuncSetAttribute(gemm_tf32_kernel<false, true,  true >,
        cudaFuncAttributeMaxDynamicSharedMemorySize, GEMM_SMEM_BYTES);
    cudaFuncSetAttribute(gemm_tf32_kernel<true,  true,  false>,
        cudaFuncAttributeMaxDynamicSharedMemorySize, GEMM_SMEM_BYTES);

    const int MB = (M + 127) / 128;          // 391
    dim3 gP(MB, 1);                          // NOUT=128
    dim3 gF1(MB, FFD / 128);                 // NOUT=512
    int edgeBlocks = (E + 7) / 8;
    int elwBlocks  = (M * ND + 255) / 256;
    int lnBlocks   = (M + 7) / 8;

    const float* xin = x;
    for (int li = 0; li < 2; li++) {
        float* xout = (li == 0) ? x1 : (float*)d_out;
        const float* wWq = Wq + (long)li * ND * ND;
        const float* wWk = Wk + (long)li * ND * ND;
        const float* wWv = Wv + (long)li * ND * ND;
        const float* wWo = Wo + (long)li * ND * ND;
        const float* wW1 = W1 + (long)li * FFD * ND;
        const float* wW2 = W2 + (long)li * ND * FFD;

        // projections
        gemm_tf32_kernel<false, true,  false><<<gP, 256, GEMM_SMEM_BYTES>>>(xin, wWq, bq + li * ND, nullptr, q, M, ND, ND);
        gemm_tf32_kernel<false, false, false><<<gP, 256, GEMM_SMEM_BYTES>>>(xin, wWk, nullptr,      nullptr, k, M, ND, ND);
        gemm_tf32_kernel<false, false, false><<<gP, 256, GEMM_SMEM_BYTES>>>(xin, wWv, nullptr,      nullptr, v, M, ND, ND);

        // attention aggregation
        cudaMemsetAsync(wv, 0, (size_t)M * ND * sizeof(float));
        cudaMemsetAsync(z,  0, (size_t)M * NH * sizeof(float));
        edge_kernel<<<edgeBlocks, 256>>>(edges, src, dst, rel, E);
        finalize_kernel<<<elwBlocks, 256>>>();

        // output proj + residual, LN1
        gemm_tf32_kernel<false, true, true><<<gP, 256, GEMM_SMEM_BYTES>>>(wv, wWo, bo + li * ND, xin, t0, M, ND, ND);
        ln_kernel<<<lnBlocks, 256>>>(t0, ln1g + li * ND, ln1b + li * ND, t1, M);

        // FFN
        gemm_tf32_kernel<true,  true, false><<<gF1, 256, GEMM_SMEM_BYTES>>>(t1, wW1, b1 + li * FFD, nullptr, ff, M, ND, FFD);
        gemm_tf32_kernel<false, true, true ><<<gP,  256, GEMM_SMEM_BYTES>>>(ff, wW2, b2 + li * ND,  t1,     t0, M, FFD, ND);
        ln_kernel<<<lnBlocks, 256>>>(t0, ln2g + li * ND, ln2b + li * ND, xout, M);

        xin = xout;
    }
}